// round 1
// baseline (speedup 1.0000x reference)
#include <cuda_runtime.h>

#define BATCH      8192
#define STATE_DIM  322
#define N_NODES    256
#define ENTRIES    27
#define ACTION     4096

// Scratch for intermediate y = tanh(node linear) : [BATCH, N_NODES], 8 MB.
__device__ float g_y[BATCH * N_NODES];

// ---------------------------------------------------------------------------
// Kernel 1: per-node gather + tiny linear + tanh.
// One block per batch row (8192 blocks), 256 threads = 256 nodes.
// State row staged in smem; W/idx reads hit L1/L2 (54 KB total, reused by all
// blocks on an SM).
// ---------------------------------------------------------------------------
__global__ __launch_bounds__(256) void node_kernel(
    const float* __restrict__ state,
    const float* __restrict__ W,
    const float* __restrict__ b,
    const int*   __restrict__ idx)
{
    __shared__ float s[STATE_DIM];
    const int row = blockIdx.x;
    const int t   = threadIdx.x;

    const float* sp = state + (long)row * STATE_DIM;
    for (int i = t; i < STATE_DIM; i += 256) s[i] = sp[i];
    __syncthreads();

    float acc = b[t];
    const int*   ip = idx + t * ENTRIES;
    const float* wp = W   + t * ENTRIES;
#pragma unroll
    for (int e = 0; e < ENTRIES; e++)
        acc = fmaf(s[ip[e]], wp[e], acc);

    g_y[(long)row * N_NODES + t] = tanhf(acc);
}

// ---------------------------------------------------------------------------
// Kernel 2: out[b][a] = 500 * sigmoid( sum_k y[b][k] * Wf[a][k] )
// Classic register-blocked fp32 SGEMM: BM=BN=128, BK=16, 256 threads,
// 8x8 accumulators per thread. Both A (y) and B (Wf) are K-major row-major,
// staged transposed into smem (padded rows: stride 132 -> no k-conflicts,
// rows stay 16B aligned so float4 smem reads are legal).
// ---------------------------------------------------------------------------
#define BM 128
#define BN 128
#define BK 16
#define TM 8
#define TN 8
#define LDP (BM + 4)   // padded leading dim (132): 132%32=4 breaks bank aliasing

__global__ __launch_bounds__(256, 2) void gemm_sig_kernel(
    const float* __restrict__ Wf,
    float*       __restrict__ out)
{
    __shared__ float As[BK][LDP];
    __shared__ float Bs[BK][LDP];

    const int n0  = blockIdx.x * BN;
    const int m0  = blockIdx.y * BM;
    const int tid = threadIdx.x;
    const int tx  = tid & 15;   // 0..15 -> N direction
    const int ty  = tid >> 4;   // 0..15 -> M direction

    // global-load coordinates: 64 rows x 16 cols per pass, float4 per thread
    const int lrow = tid >> 2;        // 0..63
    const int lcol = (tid & 3) * 4;   // 0,4,8,12

    float acc[TM][TN] = {};

    for (int k0 = 0; k0 < N_NODES; k0 += BK) {
#pragma unroll
        for (int h = 0; h < 2; h++) {
            const int r = lrow + h * 64;
            float4 va = *(const float4*)(&g_y[(long)(m0 + r) * N_NODES + k0 + lcol]);
            As[lcol + 0][r] = va.x;
            As[lcol + 1][r] = va.y;
            As[lcol + 2][r] = va.z;
            As[lcol + 3][r] = va.w;
            float4 vb = *(const float4*)(&Wf[(long)(n0 + r) * N_NODES + k0 + lcol]);
            Bs[lcol + 0][r] = vb.x;
            Bs[lcol + 1][r] = vb.y;
            Bs[lcol + 2][r] = vb.z;
            Bs[lcol + 3][r] = vb.w;
        }
        __syncthreads();

#pragma unroll
        for (int k = 0; k < BK; k++) {
            float ra[TM], rb[TN];
            // rows are 16B aligned (LDP*4 = 528 bytes, multiple of 16)
            *(float4*)&ra[0] = *(const float4*)&As[k][ty * TM + 0];
            *(float4*)&ra[4] = *(const float4*)&As[k][ty * TM + 4];
            *(float4*)&rb[0] = *(const float4*)&Bs[k][tx * TN + 0];
            *(float4*)&rb[4] = *(const float4*)&Bs[k][tx * TN + 4];
#pragma unroll
            for (int i = 0; i < TM; i++)
#pragma unroll
                for (int j = 0; j < TN; j++)
                    acc[i][j] = fmaf(ra[i], rb[j], acc[i][j]);
        }
        __syncthreads();
    }

    // Fused epilogue: 500 * sigmoid(z)
#pragma unroll
    for (int i = 0; i < TM; i++) {
        const int m = m0 + ty * TM + i;
        float* op = out + (long)m * ACTION + n0 + tx * TN;
#pragma unroll
        for (int j = 0; j < TN; j += 4) {
            float4 o;
            o.x = 500.0f / (1.0f + __expf(-acc[i][j + 0]));
            o.y = 500.0f / (1.0f + __expf(-acc[i][j + 1]));
            o.z = 500.0f / (1.0f + __expf(-acc[i][j + 2]));
            o.w = 500.0f / (1.0f + __expf(-acc[i][j + 3]));
            *(float4*)(op + j) = o;
        }
    }
}

// ---------------------------------------------------------------------------
extern "C" void kernel_launch(void* const* d_in, const int* in_sizes, int n_in,
                              void* d_out, int out_size)
{
    const float* state = (const float*)d_in[0];
    const float* W     = (const float*)d_in[1];
    const float* b     = (const float*)d_in[2];
    const float* Wf    = (const float*)d_in[3];
    const int*   idx   = (const int*)  d_in[4];
    float*       out   = (float*)d_out;

    node_kernel<<<BATCH, 256>>>(state, W, b, idx);

    dim3 grid(ACTION / BN, BATCH / BM);
    gemm_sig_kernel<<<grid, 256>>>(Wf, out);
}

// round 3
// speedup vs baseline: 2.7768x; 2.7768x over previous
#include <cuda_runtime.h>
#include <cstdint>

#define BATCH      8192
#define STATE_DIM  322
#define N_NODES    256
#define ENTRIES    27
#define ACTION     4096

// y = tanh(node linear), stored as tf32-rounded fp32 bit patterns. 8 MB.
__device__ unsigned int g_y[BATCH * N_NODES];

__device__ __forceinline__ unsigned int f2tf32(float f) {
    unsigned int r;
    asm("cvt.rna.tf32.f32 %0, %1;" : "=r"(r) : "f"(f));
    return r;
}

// ---------------------------------------------------------------------------
// Kernel 1: per-node gather + tiny linear + tanh.
// 256 threads = 256 nodes; 16 batch rows per block so each thread keeps its
// 27 weights + 27 indices in registers (amortized 16x).
// ---------------------------------------------------------------------------
#define R_PER_BLK 16

__global__ __launch_bounds__(256) void node_kernel(
    const float* __restrict__ state,
    const float* __restrict__ W,
    const float* __restrict__ b,
    const int*   __restrict__ idx)
{
    __shared__ float s[R_PER_BLK * STATE_DIM];   // 20.6 KB
    const int t    = threadIdx.x;
    const int row0 = blockIdx.x * R_PER_BLK;

    // 16 state rows are contiguous in global memory -> flat coalesced copy
    const float* sp = state + (long)row0 * STATE_DIM;
    for (int i = t; i < R_PER_BLK * STATE_DIM; i += 256) s[i] = sp[i];

    float w[ENTRIES];
    int   ix[ENTRIES];
#pragma unroll
    for (int e = 0; e < ENTRIES; e++) {
        w[e]  = W  [t * ENTRIES + e];
        ix[e] = idx[t * ENTRIES + e];
    }
    const float bb = b[t];
    __syncthreads();

#pragma unroll 4
    for (int r = 0; r < R_PER_BLK; r++) {
        const float* sr = s + r * STATE_DIM;
        float acc = bb;
#pragma unroll
        for (int e = 0; e < ENTRIES; e++)
            acc = fmaf(sr[ix[e]], w[e], acc);
        g_y[(long)(row0 + r) * N_NODES + t] = f2tf32(tanhf(acc));
    }
}

// ---------------------------------------------------------------------------
// Kernel 2: out = 500*sigmoid(y @ Wf^T) via tf32 mma.sync.m16n8k8.
// BM=BN=128, BK=32. 8 warps arranged 2(m) x 4(n); each warp owns a 64x32
// tile = 4x4 m16n8k8 fragments (64 fp32 accumulators).
// Smem rows padded to 36 floats: every fragment-load pattern hits 32
// distinct banks ((4*row + col) mod 32 is bijective over a warp).
// ---------------------------------------------------------------------------
#define BM 128
#define BN 128
#define BK 32
#define LDA 36   // BK + 4 pad

__device__ __forceinline__ void mma_tf32(
    float c[4], unsigned int a0, unsigned int a1, unsigned int a2, unsigned int a3,
    unsigned int b0, unsigned int b1)
{
    asm volatile(
        "mma.sync.aligned.m16n8k8.row.col.f32.tf32.tf32.f32 "
        "{%0,%1,%2,%3}, {%4,%5,%6,%7}, {%8,%9}, {%0,%1,%2,%3};\n"
        : "+f"(c[0]), "+f"(c[1]), "+f"(c[2]), "+f"(c[3])
        : "r"(a0), "r"(a1), "r"(a2), "r"(a3), "r"(b0), "r"(b1));
}

__global__ __launch_bounds__(256, 2) void gemm_sig_kernel(
    const float* __restrict__ Wf,
    float*       __restrict__ out)
{
    __shared__ unsigned int As[BM][LDA];   // 18.4 KB
    __shared__ unsigned int Bs[BN][LDA];   // 18.4 KB

    const int tid    = threadIdx.x;
    const int lane   = tid & 31;
    const int wid    = tid >> 5;
    const int warp_m = wid >> 2;           // 0..1 -> 64-row half
    const int warp_n = wid & 3;            // 0..3 -> 32-col quarter
    const int n0     = blockIdx.x * BN;
    const int m0     = blockIdx.y * BM;

    const int frow = lane >> 2;            // 0..7
    const int fcol = lane & 3;             // 0..3

    // global staging coords: 8 threads per row (32 floats), 4 passes of 32 rows
    const int lr = tid >> 3;               // 0..31
    const int lc = (tid & 7) * 4;          // 0,4,...,28

    float acc[4][4][4] = {};

    for (int k0 = 0; k0 < N_NODES; k0 += BK) {
#pragma unroll
        for (int h = 0; h < 4; h++) {
            const int r = lr + h * 32;
            uint4 va = *(const uint4*)&g_y[(long)(m0 + r) * N_NODES + k0 + lc];
            *(uint4*)&As[r][lc] = va;      // already tf32-rounded
            float4 vb = *(const float4*)&Wf[(long)(n0 + r) * N_NODES + k0 + lc];
            uint4 ub = { f2tf32(vb.x), f2tf32(vb.y), f2tf32(vb.z), f2tf32(vb.w) };
            *(uint4*)&Bs[r][lc] = ub;
        }
        __syncthreads();

#pragma unroll
        for (int ks = 0; ks < BK; ks += 8) {
            unsigned int a[4][4], bf[4][2];
#pragma unroll
            for (int mt = 0; mt < 4; mt++) {
                const int mr = warp_m * 64 + mt * 16 + frow;
                a[mt][0] = As[mr    ][ks + fcol    ];
                a[mt][1] = As[mr + 8][ks + fcol    ];
                a[mt][2] = As[mr    ][ks + fcol + 4];
                a[mt][3] = As[mr + 8][ks + fcol + 4];
            }
#pragma unroll
            for (int nt = 0; nt < 4; nt++) {
                const int nr = warp_n * 32 + nt * 8 + frow;
                bf[nt][0] = Bs[nr][ks + fcol    ];
                bf[nt][1] = Bs[nr][ks + fcol + 4];
            }
#pragma unroll
            for (int mt = 0; mt < 4; mt++)
#pragma unroll
                for (int nt = 0; nt < 4; nt++)
                    mma_tf32(acc[mt][nt], a[mt][0], a[mt][1], a[mt][2], a[mt][3],
                             bf[nt][0], bf[nt][1]);
        }
        __syncthreads();
    }

    // Epilogue: 500*sigmoid, fragment layout c0,c1 @ (row, 2*fcol), c2,c3 @ row+8
#pragma unroll
    for (int mt = 0; mt < 4; mt++) {
#pragma unroll
        for (int nt = 0; nt < 4; nt++) {
            const int m = m0 + warp_m * 64 + mt * 16 + frow;
            const int n = n0 + warp_n * 32 + nt * 8 + 2 * fcol;
            float2 o0, o1;
            o0.x = 500.0f / (1.0f + __expf(-acc[mt][nt][0]));
            o0.y = 500.0f / (1.0f + __expf(-acc[mt][nt][1]));
            o1.x = 500.0f / (1.0f + __expf(-acc[mt][nt][2]));
            o1.y = 500.0f / (1.0f + __expf(-acc[mt][nt][3]));
            *(float2*)&out[(long)m * ACTION + n]       = o0;
            *(float2*)&out[(long)(m + 8) * ACTION + n] = o1;
        }
    }
}

// ---------------------------------------------------------------------------
extern "C" void kernel_launch(void* const* d_in, const int* in_sizes, int n_in,
                              void* d_out, int out_size)
{
    const float* state = (const float*)d_in[0];
    const float* W     = (const float*)d_in[1];
    const float* b     = (const float*)d_in[2];
    const float* Wf    = (const float*)d_in[3];
    const int*   idx   = (const int*)  d_in[4];
    float*       out   = (float*)d_out;

    node_kernel<<<BATCH / R_PER_BLK, 256>>>(state, W, b, idx);

    dim3 grid(ACTION / BN, BATCH / BM);
    gemm_sig_kernel<<<grid, 256>>>(Wf, out);
}

// round 5
// speedup vs baseline: 2.9873x; 1.0758x over previous
#include <cuda_runtime.h>
#include <cuda_bf16.h>
#include <cstdint>

#define BATCH      8192
#define STATE_DIM  322
#define N_NODES    256
#define ENTRIES    27
#define ACTION     4096

// Intermediates: y as bf16 [BATCH][256] (4 MB), Wf as bf16 [4096][256] (2 MB)
__device__ __nv_bfloat16 g_y [BATCH  * N_NODES];
__device__ __nv_bfloat16 g_wf[ACTION * N_NODES];

__device__ __forceinline__ uint32_t smem_u32(const void* p) {
    uint32_t a;
    asm("{ .reg .u64 t; cvta.to.shared.u64 t, %1; cvt.u32.u64 %0, t; }" : "=r"(a) : "l"(p));
    return a;
}
#define CP_ASYNC16(dst, src) \
    asm volatile("cp.async.cg.shared.global [%0], [%1], 16;" :: "r"(dst), "l"(src))
#define CP_COMMIT()  asm volatile("cp.async.commit_group;" ::: "memory")
#define CP_WAIT(N)   asm volatile("cp.async.wait_group %0;" :: "n"(N) : "memory")

__device__ __forceinline__ void ldmx4(uint32_t* r, uint32_t addr) {
    asm volatile("ldmatrix.sync.aligned.m8n8.x4.shared.b16 {%0,%1,%2,%3}, [%4];"
                 : "=r"(r[0]), "=r"(r[1]), "=r"(r[2]), "=r"(r[3]) : "r"(addr));
}
__device__ __forceinline__ void ldmx2(uint32_t* r, uint32_t addr) {
    asm volatile("ldmatrix.sync.aligned.m8n8.x2.shared.b16 {%0,%1}, [%2];"
                 : "=r"(r[0]), "=r"(r[1]) : "r"(addr));
}
__device__ __forceinline__ void mma_bf16(float c[4], const uint32_t a[4], const uint32_t b[2]) {
    asm volatile(
        "mma.sync.aligned.m16n8k16.row.col.f32.bf16.bf16.f32 "
        "{%0,%1,%2,%3}, {%4,%5,%6,%7}, {%8,%9}, {%0,%1,%2,%3};"
        : "+f"(c[0]), "+f"(c[1]), "+f"(c[2]), "+f"(c[3])
        : "r"(a[0]), "r"(a[1]), "r"(a[2]), "r"(a[3]), "r"(b[0]), "r"(b[1]));
}

// ---------------------------------------------------------------------------
// Kernel 0: Wf fp32 -> bf16
// ---------------------------------------------------------------------------
__global__ __launch_bounds__(256) void wf_convert(const float* __restrict__ Wf) {
    int i = (blockIdx.x * 256 + threadIdx.x) * 4;
    float4 v = *(const float4*)(Wf + i);
    __nv_bfloat162* p = (__nv_bfloat162*)(g_wf + i);
    p[0] = __floats2bfloat162_rn(v.x, v.y);
    p[1] = __floats2bfloat162_rn(v.z, v.w);
}

// ---------------------------------------------------------------------------
// Kernel 1: per-node gather + tiny linear + tanh -> bf16
// ---------------------------------------------------------------------------
#define R_PER_BLK 16
__global__ __launch_bounds__(256) void node_kernel(
    const float* __restrict__ state, const float* __restrict__ W,
    const float* __restrict__ b,     const int*   __restrict__ idx)
{
    __shared__ float s[R_PER_BLK * STATE_DIM];
    const int t = threadIdx.x, row0 = blockIdx.x * R_PER_BLK;
    const float* sp = state + (long)row0 * STATE_DIM;
    for (int i = t; i < R_PER_BLK * STATE_DIM; i += 256) s[i] = sp[i];

    float w[ENTRIES]; int ix[ENTRIES];
#pragma unroll
    for (int e = 0; e < ENTRIES; e++) { w[e] = W[t*ENTRIES+e]; ix[e] = idx[t*ENTRIES+e]; }
    const float bb = b[t];
    __syncthreads();
#pragma unroll 4
    for (int r = 0; r < R_PER_BLK; r++) {
        const float* sr = s + r * STATE_DIM;
        float acc = bb;
#pragma unroll
        for (int e = 0; e < ENTRIES; e++) acc = fmaf(sr[ix[e]], w[e], acc);
        g_y[(long)(row0 + r) * N_NODES + t] = __float2bfloat16(tanhf(acc));
    }
}

// ---------------------------------------------------------------------------
// Kernel 2: out = 500*sigmoid(y @ Wf^T), bf16 mma.sync.m16n8k16.
// BM=BN=128, BK=64, 2-stage cp.async pipeline. 8 warps 2(m) x 4(n), each warp
// 64x32 = 4x4 m16n8k16 fragments. Smem rows padded to 72 bf16 (144 B): each
// ldmatrix 8-row phase covers 32 distinct banks.
// ---------------------------------------------------------------------------
#define BK      64
#define LDK     72                     // bf16 elems per smem row
#define ROWB    (LDK * 2)              // 144 bytes
#define TILE_B  (128 * ROWB)           // 18432 bytes per operand tile
#define STAGE_B (2 * TILE_B)           // A + B per stage
#define SMEM_SZ (2 * STAGE_B)          // 73728 bytes

__global__ __launch_bounds__(256, 2) void gemm_sig_kernel(float* __restrict__ out)
{
    extern __shared__ char smem[];
    const uint32_t sb   = smem_u32(smem);
    const int tid  = threadIdx.x;
    const int lane = tid & 31;
    const int wid  = tid >> 5;
    const int warp_m = wid >> 2;       // 0..1
    const int warp_n = wid & 3;        // 0..3
    const int n0 = blockIdx.x * 128;
    const int m0 = blockIdx.y * 128;

    // staging coords: 1024 16B-chunks per tile, 4 per thread
    const int srow = tid >> 1;                 // pairs: 2 threads per row? no:
    // e = tid + i*256 ; row = e>>3 (0..127), c = e&7 (16B chunk)
    const __nv_bfloat16* gA = g_y  + (size_t)m0 * N_NODES;
    const __nv_bfloat16* gB = g_wf + (size_t)n0 * N_NODES;
    (void)srow;

    float acc[4][4][4] = {};

    // per-thread ldmatrix base addresses (stage 0, kc 0)
    uint32_t a_base[4], b_base[4];
#pragma unroll
    for (int mt = 0; mt < 4; mt++)
        a_base[mt] = sb + (warp_m * 64 + mt * 16 + (lane & 15)) * ROWB + (lane >> 4) * 16;
#pragma unroll
    for (int nt = 0; nt < 4; nt++)
        b_base[nt] = sb + TILE_B + (warp_n * 32 + nt * 8 + (lane & 7)) * ROWB
                   + ((lane >> 3) & 1) * 16;

    // ---- prologue: stage 0 ----
#pragma unroll
    for (int i = 0; i < 4; i++) {
        const int e = tid + i * 256, r = e >> 3, c = e & 7;
        const uint32_t so = r * ROWB + c * 16;
        CP_ASYNC16(sb + so,          (const void*)(gA + (size_t)r * N_NODES + c * 8));
        CP_ASYNC16(sb + TILE_B + so, (const void*)(gB + (size_t)r * N_NODES + c * 8));
    }
    CP_COMMIT();

    int buf = 0;
#pragma unroll
    for (int it = 0; it < 4; it++) {
        if (it < 3) {
            const int k0 = (it + 1) * BK;
            const uint32_t dst = sb + (buf ^ 1) * STAGE_B;
#pragma unroll
            for (int i = 0; i < 4; i++) {
                const int e = tid + i * 256, r = e >> 3, c = e & 7;
                const uint32_t so = r * ROWB + c * 16;
                CP_ASYNC16(dst + so,          (const void*)(gA + (size_t)r * N_NODES + k0 + c * 8));
                CP_ASYNC16(dst + TILE_B + so, (const void*)(gB + (size_t)r * N_NODES + k0 + c * 8));
            }
            CP_COMMIT();
            CP_WAIT(1);
        } else {
            CP_WAIT(0);
        }
        __syncthreads();

        const uint32_t soff = buf * STAGE_B;
#pragma unroll
        for (int kc = 0; kc < 4; kc++) {
            uint32_t a[4][4], bfr[4][2];
#pragma unroll
            for (int mt = 0; mt < 4; mt++) ldmx4(a[mt],   a_base[mt] + soff + kc * 32);
#pragma unroll
            for (int nt = 0; nt < 4; nt++) ldmx2(bfr[nt], b_base[nt] + soff + kc * 32);
#pragma unroll
            for (int mt = 0; mt < 4; mt++)
#pragma unroll
                for (int nt = 0; nt < 4; nt++)
                    mma_bf16(acc[mt][nt], a[mt], bfr[nt]);
        }
        buf ^= 1;
        if (it < 3) __syncthreads();
    }

    // Epilogue: 500*sigmoid; frag c0,c1 @ (row frow, col 2*fcol), c2,c3 @ row+8
    const int frow = lane >> 2, fcol = lane & 3;
#pragma unroll
    for (int mt = 0; mt < 4; mt++) {
#pragma unroll
        for (int nt = 0; nt < 4; nt++) {
            const int m = m0 + warp_m * 64 + mt * 16 + frow;
            const int n = n0 + warp_n * 32 + nt * 8 + 2 * fcol;
            float2 o0, o1;
            o0.x = 500.0f / (1.0f + __expf(-acc[mt][nt][0]));
            o0.y = 500.0f / (1.0f + __expf(-acc[mt][nt][1]));
            o1.x = 500.0f / (1.0f + __expf(-acc[mt][nt][2]));
            o1.y = 500.0f / (1.0f + __expf(-acc[mt][nt][3]));
            *(float2*)&out[(size_t)m * ACTION + n]       = o0;
            *(float2*)&out[(size_t)(m + 8) * ACTION + n] = o1;
        }
    }
}

// ---------------------------------------------------------------------------
extern "C" void kernel_launch(void* const* d_in, const int* in_sizes, int n_in,
                              void* d_out, int out_size)
{
    const float* state = (const float*)d_in[0];
    const float* W     = (const float*)d_in[1];
    const float* b     = (const float*)d_in[2];
    const float* Wf    = (const float*)d_in[3];
    const int*   idx   = (const int*)  d_in[4];
    float*       out   = (float*)d_out;

    cudaFuncSetAttribute(gemm_sig_kernel,
                         cudaFuncAttributeMaxDynamicSharedMemorySize, SMEM_SZ);

    wf_convert<<<ACTION * N_NODES / 1024, 256>>>(Wf);
    node_kernel<<<BATCH / R_PER_BLK, 256>>>(state, W, b, idx);

    dim3 grid(ACTION / 128, BATCH / 128);
    gemm_sig_kernel<<<grid, 256, SMEM_SZ>>>(out);
}

// round 6
// speedup vs baseline: 3.6711x; 1.2289x over previous
#include <cuda_runtime.h>
#include <cuda_bf16.h>
#include <cstdint>

#define BATCH      8192
#define STATE_DIM  322
#define N_NODES    256
#define ENTRIES    27
#define ACTION     4096

// Intermediates: y as bf16 [BATCH][256] (4 MB), Wf as bf16 [4096][256] (2 MB)
__device__ __nv_bfloat16 g_y [BATCH  * N_NODES];
__device__ __nv_bfloat16 g_wf[ACTION * N_NODES];

__device__ __forceinline__ uint32_t smem_u32(const void* p) {
    uint32_t a;
    asm("{ .reg .u64 t; cvta.to.shared.u64 t, %1; cvt.u32.u64 %0, t; }" : "=r"(a) : "l"(p));
    return a;
}
#define CP_ASYNC16(dst, src) \
    asm volatile("cp.async.cg.shared.global [%0], [%1], 16;" :: "r"(dst), "l"(src))
#define CP_COMMIT()  asm volatile("cp.async.commit_group;" ::: "memory")
#define CP_WAIT(N)   asm volatile("cp.async.wait_group %0;" :: "n"(N) : "memory")

__device__ __forceinline__ void ldmx4(uint32_t* r, uint32_t addr) {
    asm volatile("ldmatrix.sync.aligned.m8n8.x4.shared.b16 {%0,%1,%2,%3}, [%4];"
                 : "=r"(r[0]), "=r"(r[1]), "=r"(r[2]), "=r"(r[3]) : "r"(addr));
}
__device__ __forceinline__ void mma_bf16(float c[4], const uint32_t a[4],
                                         uint32_t b0, uint32_t b1) {
    asm volatile(
        "mma.sync.aligned.m16n8k16.row.col.f32.bf16.bf16.f32 "
        "{%0,%1,%2,%3}, {%4,%5,%6,%7}, {%8,%9}, {%0,%1,%2,%3};"
        : "+f"(c[0]), "+f"(c[1]), "+f"(c[2]), "+f"(c[3])
        : "r"(a[0]), "r"(a[1]), "r"(a[2]), "r"(a[3]), "r"(b0), "r"(b1));
}

// ---------------------------------------------------------------------------
// Kernel 0: Wf fp32 -> bf16
// ---------------------------------------------------------------------------
__global__ __launch_bounds__(256) void wf_convert(const float* __restrict__ Wf) {
    int i = (blockIdx.x * 256 + threadIdx.x) * 4;
    float4 v = *(const float4*)(Wf + i);
    __nv_bfloat162* p = (__nv_bfloat162*)(g_wf + i);
    p[0] = __floats2bfloat162_rn(v.x, v.y);
    p[1] = __floats2bfloat162_rn(v.z, v.w);
}

// ---------------------------------------------------------------------------
// Kernel 1: per-node gather + tiny linear + tanh -> bf16
// ---------------------------------------------------------------------------
#define R_PER_BLK 16
__global__ __launch_bounds__(256) void node_kernel(
    const float* __restrict__ state, const float* __restrict__ W,
    const float* __restrict__ b,     const int*   __restrict__ idx)
{
    __shared__ float s[R_PER_BLK * STATE_DIM];
    const int t = threadIdx.x, row0 = blockIdx.x * R_PER_BLK;
    const float* sp = state + (long)row0 * STATE_DIM;
    for (int i = t; i < R_PER_BLK * STATE_DIM; i += 256) s[i] = sp[i];

    float w[ENTRIES]; int ix[ENTRIES];
#pragma unroll
    for (int e = 0; e < ENTRIES; e++) { w[e] = W[t*ENTRIES+e]; ix[e] = idx[t*ENTRIES+e]; }
    const float bb = b[t];
    __syncthreads();
#pragma unroll 4
    for (int r = 0; r < R_PER_BLK; r++) {
        const float* sr = s + r * STATE_DIM;
        float acc = bb;
#pragma unroll
        for (int e = 0; e < ENTRIES; e++) acc = fmaf(sr[ix[e]], w[e], acc);
        g_y[(long)(row0 + r) * N_NODES + t] = __float2bfloat16(tanhf(acc));
    }
}

// ---------------------------------------------------------------------------
// Kernel 2: out = 500*sigmoid(y @ Wf^T), bf16 mma.sync.m16n8k16.
// CTA tile 128(m) x 256(n), BK=64, 2-stage cp.async pipeline.
// 8 warps 2(m) x 4(n); warp tile 64x64 = 4(mt) x 8(nt) fragments, 128 accums.
// B loaded with ldmatrix.x4 covering two n-tiles per load -> LDSM:HMMA = 1:4.
// Smem rows padded to 144 B: every 8-row ldmatrix phase spans 32 banks.
// ---------------------------------------------------------------------------
#define BK      64
#define ROWB    144                    // 72 bf16 per row
#define TILE_A  (128 * ROWB)           // 18432 B
#define TILE_BB (256 * ROWB)           // 36864 B
#define STAGE_B (TILE_A + TILE_BB)     // 55296 B
#define SMEM_SZ (2 * STAGE_B)          // 110592 B

__global__ __launch_bounds__(256, 1) void gemm_sig_kernel(float* __restrict__ out)
{
    extern __shared__ char smem[];
    const uint32_t sb = smem_u32(smem);
    const int tid    = threadIdx.x;
    const int lane   = tid & 31;
    const int wid    = tid >> 5;
    const int warp_m = wid >> 2;       // 0..1 -> 64-row half
    const int warp_n = wid & 3;        // 0..3 -> 64-col quarter
    const int n0 = blockIdx.x * 256;
    const int m0 = blockIdx.y * 128;

    const __nv_bfloat16* gA = g_y  + (size_t)m0 * N_NODES;
    const __nv_bfloat16* gB = g_wf + (size_t)n0 * N_NODES;

    float acc[4][8][4] = {};

    // ldmatrix base addresses (stage 0, kc 0)
    // A x4: lanes 0-15 -> rows (m), lanes 16-31 -> +16B in k
    uint32_t a_base[4];
#pragma unroll
    for (int mt = 0; mt < 4; mt++)
        a_base[mt] = sb + (warp_m * 64 + mt * 16 + (lane & 15)) * ROWB + (lane >> 4) * 16;
    // B x4 (two n-tiles): lanes 0-7 n[0:8]k0, 8-15 n[0:8]k8, 16-23 n[8:16]k0, 24-31 n[8:16]k8
    uint32_t b_base[4];
#pragma unroll
    for (int p = 0; p < 4; p++)
        b_base[p] = sb + TILE_A
                  + (warp_n * 64 + p * 16 + ((lane >> 4) & 1) * 8 + (lane & 7)) * ROWB
                  + ((lane >> 3) & 1) * 16;

    // ---- prologue: stage 0 ----
#pragma unroll
    for (int i = 0; i < 4; i++) {            // A: 1024 chunks
        const int e = tid + i * 256, r = e >> 3, c = e & 7;
        CP_ASYNC16(sb + r * ROWB + c * 16, (const void*)(gA + (size_t)r * N_NODES + c * 8));
    }
#pragma unroll
    for (int i = 0; i < 8; i++) {            // B: 2048 chunks
        const int e = tid + i * 256, r = e >> 3, c = e & 7;
        CP_ASYNC16(sb + TILE_A + r * ROWB + c * 16,
                   (const void*)(gB + (size_t)r * N_NODES + c * 8));
    }
    CP_COMMIT();

    int buf = 0;
#pragma unroll
    for (int it = 0; it < 4; it++) {
        if (it < 3) {
            const int k0 = (it + 1) * BK;
            const uint32_t dst = sb + (buf ^ 1) * STAGE_B;
#pragma unroll
            for (int i = 0; i < 4; i++) {
                const int e = tid + i * 256, r = e >> 3, c = e & 7;
                CP_ASYNC16(dst + r * ROWB + c * 16,
                           (const void*)(gA + (size_t)r * N_NODES + k0 + c * 8));
            }
#pragma unroll
            for (int i = 0; i < 8; i++) {
                const int e = tid + i * 256, r = e >> 3, c = e & 7;
                CP_ASYNC16(dst + TILE_A + r * ROWB + c * 16,
                           (const void*)(gB + (size_t)r * N_NODES + k0 + c * 8));
            }
            CP_COMMIT();
            CP_WAIT(1);
        } else {
            CP_WAIT(0);
        }
        __syncthreads();

        const uint32_t soff = buf * STAGE_B;
#pragma unroll
        for (int kc = 0; kc < 4; kc++) {
            uint32_t a[4][4], bp[4][4];
#pragma unroll
            for (int mt = 0; mt < 4; mt++) ldmx4(a[mt],  a_base[mt] + soff + kc * 32);
#pragma unroll
            for (int p = 0; p < 4; p++)    ldmx4(bp[p],  b_base[p]  + soff + kc * 32);
#pragma unroll
            for (int mt = 0; mt < 4; mt++)
#pragma unroll
                for (int nt = 0; nt < 8; nt++)
                    mma_bf16(acc[mt][nt], a[mt],
                             bp[nt >> 1][(nt & 1) * 2], bp[nt >> 1][(nt & 1) * 2 + 1]);
        }
        buf ^= 1;
        if (it < 3) __syncthreads();
    }

    // Epilogue: 500*sigmoid; frag c0,c1 @ (frow, 2*fcol), c2,c3 @ frow+8
    const int frow = lane >> 2, fcol = lane & 3;
#pragma unroll
    for (int mt = 0; mt < 4; mt++) {
        const int m = m0 + warp_m * 64 + mt * 16 + frow;
#pragma unroll
        for (int nt = 0; nt < 8; nt++) {
            const int n = n0 + warp_n * 64 + nt * 8 + 2 * fcol;
            float2 o0, o1;
            o0.x = 500.0f / (1.0f + __expf(-acc[mt][nt][0]));
            o0.y = 500.0f / (1.0f + __expf(-acc[mt][nt][1]));
            o1.x = 500.0f / (1.0f + __expf(-acc[mt][nt][2]));
            o1.y = 500.0f / (1.0f + __expf(-acc[mt][nt][3]));
            *(float2*)&out[(size_t)m * ACTION + n]       = o0;
            *(float2*)&out[(size_t)(m + 8) * ACTION + n] = o1;
        }
    }
}

// ---------------------------------------------------------------------------
extern "C" void kernel_launch(void* const* d_in, const int* in_sizes, int n_in,
                              void* d_out, int out_size)
{
    const float* state = (const float*)d_in[0];
    const float* W     = (const float*)d_in[1];
    const float* b     = (const float*)d_in[2];
    const float* Wf    = (const float*)d_in[3];
    const int*   idx   = (const int*)  d_in[4];
    float*       out   = (float*)d_out;

    cudaFuncSetAttribute(gemm_sig_kernel,
                         cudaFuncAttributeMaxDynamicSharedMemorySize, SMEM_SZ);

    wf_convert<<<ACTION * N_NODES / 1024, 256>>>(Wf);
    node_kernel<<<BATCH / R_PER_BLK, 256>>>(state, W, b, idx);

    dim3 grid(ACTION / 256, BATCH / 128);
    gemm_sig_kernel<<<grid, 256, SMEM_SZ>>>(out);
}

// round 7
// speedup vs baseline: 4.7239x; 1.2868x over previous
#include <cuda_runtime.h>
#include <cuda_bf16.h>
#include <cstdint>

#define BATCH      8192
#define STATE_DIM  322
#define N_NODES    256
#define ENTRIES    27
#define ACTION     4096

// Intermediates: y as bf16 [BATCH][256] (4 MB), Wf as bf16 [4096][256] (2 MB)
__device__ __nv_bfloat16 g_y [BATCH  * N_NODES];
__device__ __nv_bfloat16 g_wf[ACTION * N_NODES];

__device__ __forceinline__ uint32_t smem_u32(const void* p) {
    uint32_t a;
    asm("{ .reg .u64 t; cvta.to.shared.u64 t, %1; cvt.u32.u64 %0, t; }" : "=r"(a) : "l"(p));
    return a;
}
#define CP_ASYNC16(dst, src) \
    asm volatile("cp.async.cg.shared.global [%0], [%1], 16;" :: "r"(dst), "l"(src))
#define CP_COMMIT()  asm volatile("cp.async.commit_group;" ::: "memory")
#define CP_WAIT(N)   asm volatile("cp.async.wait_group %0;" :: "n"(N) : "memory")

__device__ __forceinline__ void ldmx4(uint32_t* r, uint32_t addr) {
    asm volatile("ldmatrix.sync.aligned.m8n8.x4.shared.b16 {%0,%1,%2,%3}, [%4];"
                 : "=r"(r[0]), "=r"(r[1]), "=r"(r[2]), "=r"(r[3]) : "r"(addr));
}
__device__ __forceinline__ void mma_bf16(float c[4], const uint32_t a[4],
                                         uint32_t b0, uint32_t b1) {
    asm volatile(
        "mma.sync.aligned.m16n8k16.row.col.f32.bf16.bf16.f32 "
        "{%0,%1,%2,%3}, {%4,%5,%6,%7}, {%8,%9}, {%0,%1,%2,%3};"
        : "+f"(c[0]), "+f"(c[1]), "+f"(c[2]), "+f"(c[3])
        : "r"(a[0]), "r"(a[1]), "r"(a[2]), "r"(a[3]), "r"(b0), "r"(b1));
}

// ---------------------------------------------------------------------------
// Kernel 1: fused prep.
//   blocks [0, 512):    per-node gather + tiny linear + tanh -> g_y (bf16)
//   blocks [512, 1536): Wf fp32 -> bf16 -> g_wf
// ---------------------------------------------------------------------------
#define R_PER_BLK  16
#define NODE_BLKS  (BATCH / R_PER_BLK)          // 512
#define CONV_BLKS  (ACTION * N_NODES / 1024)    // 1024

__global__ __launch_bounds__(256) void prep_kernel(
    const float* __restrict__ state, const float* __restrict__ W,
    const float* __restrict__ b,     const int*   __restrict__ idx,
    const float* __restrict__ Wf)
{
    if (blockIdx.x >= NODE_BLKS) {
        // ---- Wf convert ----
        const int i = ((blockIdx.x - NODE_BLKS) * 256 + threadIdx.x) * 4;
        float4 v = *(const float4*)(Wf + i);
        __nv_bfloat162* p = (__nv_bfloat162*)(g_wf + i);
        p[0] = __floats2bfloat162_rn(v.x, v.y);
        p[1] = __floats2bfloat162_rn(v.z, v.w);
        return;
    }
    // ---- node forward ----
    __shared__ float s[R_PER_BLK * STATE_DIM];
    const int t = threadIdx.x, row0 = blockIdx.x * R_PER_BLK;
    const float* sp = state + (long)row0 * STATE_DIM;
    for (int i = t; i < R_PER_BLK * STATE_DIM; i += 256) s[i] = sp[i];

    float w[ENTRIES]; int ix[ENTRIES];
#pragma unroll
    for (int e = 0; e < ENTRIES; e++) { w[e] = W[t*ENTRIES+e]; ix[e] = idx[t*ENTRIES+e]; }
    const float bb = b[t];
    __syncthreads();
#pragma unroll 4
    for (int r = 0; r < R_PER_BLK; r++) {
        const float* sr = s + r * STATE_DIM;
        float acc = bb;
#pragma unroll
        for (int e = 0; e < ENTRIES; e++) acc = fmaf(sr[ix[e]], w[e], acc);
        g_y[(long)(row0 + r) * N_NODES + t] = __float2bfloat16(tanhf(acc));
    }
}

// ---------------------------------------------------------------------------
// Kernel 2: out = 500*sigmoid(y @ Wf^T), bf16 mma.sync.m16n8k16.
// CTA tile 128(m) x 256(n), BK=64, 2-stage cp.async pipeline.
// 8 warps 2(m) x 4(n); warp tile 64x64 = 4(mt) x 8(nt) fragments, 128 accums.
// B loaded with ldmatrix.x4 covering two n-tiles per load -> LDSM:HMMA = 1:4.
// Smem rows padded to 144 B: every 8-row ldmatrix phase spans 32 banks.
// ---------------------------------------------------------------------------
#define BK      64
#define ROWB    144                    // 72 bf16 per row
#define TILE_A  (128 * ROWB)           // 18432 B
#define TILE_BB (256 * ROWB)           // 36864 B
#define STAGE_B (TILE_A + TILE_BB)     // 55296 B
#define SMEM_SZ (2 * STAGE_B)          // 110592 B

__global__ __launch_bounds__(256, 1) void gemm_sig_kernel(float* __restrict__ out)
{
    extern __shared__ char smem[];
    const uint32_t sb = smem_u32(smem);
    const int tid    = threadIdx.x;
    const int lane   = tid & 31;
    const int wid    = tid >> 5;
    const int warp_m = wid >> 2;       // 0..1 -> 64-row half
    const int warp_n = wid & 3;        // 0..3 -> 64-col quarter
    const int n0 = blockIdx.x * 256;
    const int m0 = blockIdx.y * 128;

    const __nv_bfloat16* gA = g_y  + (size_t)m0 * N_NODES;
    const __nv_bfloat16* gB = g_wf + (size_t)n0 * N_NODES;

    float acc[4][8][4] = {};

    uint32_t a_base[4];
#pragma unroll
    for (int mt = 0; mt < 4; mt++)
        a_base[mt] = sb + (warp_m * 64 + mt * 16 + (lane & 15)) * ROWB + (lane >> 4) * 16;
    uint32_t b_base[4];
#pragma unroll
    for (int p = 0; p < 4; p++)
        b_base[p] = sb + TILE_A
                  + (warp_n * 64 + p * 16 + ((lane >> 4) & 1) * 8 + (lane & 7)) * ROWB
                  + ((lane >> 3) & 1) * 16;

    // ---- prologue: stage 0 ----
#pragma unroll
    for (int i = 0; i < 4; i++) {
        const int e = tid + i * 256, r = e >> 3, c = e & 7;
        CP_ASYNC16(sb + r * ROWB + c * 16, (const void*)(gA + (size_t)r * N_NODES + c * 8));
    }
#pragma unroll
    for (int i = 0; i < 8; i++) {
        const int e = tid + i * 256, r = e >> 3, c = e & 7;
        CP_ASYNC16(sb + TILE_A + r * ROWB + c * 16,
                   (const void*)(gB + (size_t)r * N_NODES + c * 8));
    }
    CP_COMMIT();

    int buf = 0;
#pragma unroll
    for (int it = 0; it < 4; it++) {
        if (it < 3) {
            const int k0 = (it + 1) * BK;
            const uint32_t dst = sb + (buf ^ 1) * STAGE_B;
#pragma unroll
            for (int i = 0; i < 4; i++) {
                const int e = tid + i * 256, r = e >> 3, c = e & 7;
                CP_ASYNC16(dst + r * ROWB + c * 16,
                           (const void*)(gA + (size_t)r * N_NODES + k0 + c * 8));
            }
#pragma unroll
            for (int i = 0; i < 8; i++) {
                const int e = tid + i * 256, r = e >> 3, c = e & 7;
                CP_ASYNC16(dst + TILE_A + r * ROWB + c * 16,
                           (const void*)(gB + (size_t)r * N_NODES + k0 + c * 8));
            }
            CP_COMMIT();
            CP_WAIT(1);
        } else {
            CP_WAIT(0);
        }
        __syncthreads();

        const uint32_t soff = buf * STAGE_B;
#pragma unroll
        for (int kc = 0; kc < 4; kc++) {
            uint32_t a[4][4], bp[4][4];
#pragma unroll
            for (int mt = 0; mt < 4; mt++) ldmx4(a[mt],  a_base[mt] + soff + kc * 32);
#pragma unroll
            for (int p = 0; p < 4; p++)    ldmx4(bp[p],  b_base[p]  + soff + kc * 32);
#pragma unroll
            for (int mt = 0; mt < 4; mt++)
#pragma unroll
                for (int nt = 0; nt < 8; nt++)
                    mma_bf16(acc[mt][nt], a[mt],
                             bp[nt >> 1][(nt & 1) * 2], bp[nt >> 1][(nt & 1) * 2 + 1]);
        }
        buf ^= 1;
        if (it < 3) __syncthreads();
    }

    // Epilogue: 500*sigmoid via MUFU rcp (no IEEE div).
    const int frow = lane >> 2, fcol = lane & 3;
#pragma unroll
    for (int mt = 0; mt < 4; mt++) {
        const int m = m0 + warp_m * 64 + mt * 16 + frow;
#pragma unroll
        for (int nt = 0; nt < 8; nt++) {
            const int n = n0 + warp_n * 64 + nt * 8 + 2 * fcol;
            float2 o0, o1;
            o0.x = __fdividef(500.0f, 1.0f + __expf(-acc[mt][nt][0]));
            o0.y = __fdividef(500.0f, 1.0f + __expf(-acc[mt][nt][1]));
            o1.x = __fdividef(500.0f, 1.0f + __expf(-acc[mt][nt][2]));
            o1.y = __fdividef(500.0f, 1.0f + __expf(-acc[mt][nt][3]));
            *(float2*)&out[(size_t)m * ACTION + n]       = o0;
            *(float2*)&out[(size_t)(m + 8) * ACTION + n] = o1;
        }
    }
}

// ---------------------------------------------------------------------------
extern "C" void kernel_launch(void* const* d_in, const int* in_sizes, int n_in,
                              void* d_out, int out_size)
{
    const float* state = (const float*)d_in[0];
    const float* W     = (const float*)d_in[1];
    const float* b     = (const float*)d_in[2];
    const float* Wf    = (const float*)d_in[3];
    const int*   idx   = (const int*)  d_in[4];
    float*       out   = (float*)d_out;

    cudaFuncSetAttribute(gemm_sig_kernel,
                         cudaFuncAttributeMaxDynamicSharedMemorySize, SMEM_SZ);

    prep_kernel<<<NODE_BLKS + CONV_BLKS, 256>>>(state, W, b, idx, Wf);

    dim3 grid(ACTION / 256, BATCH / 128);
    gemm_sig_kernel<<<grid, 256, SMEM_SZ>>>(out);
}

// round 8
// speedup vs baseline: 5.0460x; 1.0682x over previous
#include <cuda_runtime.h>
#include <cuda_bf16.h>
#include <cstdint>

#define BATCH      8192
#define STATE_DIM  322
#define N_NODES    256
#define ENTRIES    27
#define ACTION     4096

// Intermediates: y as bf16 [BATCH][256] (4 MB), Wf as bf16 [4096][256] (2 MB)
__device__ __nv_bfloat16 g_y [BATCH  * N_NODES];
__device__ __nv_bfloat16 g_wf[ACTION * N_NODES];

__device__ __forceinline__ uint32_t smem_u32(const void* p) {
    uint32_t a;
    asm("{ .reg .u64 t; cvta.to.shared.u64 t, %1; cvt.u32.u64 %0, t; }" : "=r"(a) : "l"(p));
    return a;
}
#define CP_ASYNC16(dst, src) \
    asm volatile("cp.async.cg.shared.global [%0], [%1], 16;" :: "r"(dst), "l"(src))
#define CP_COMMIT()  asm volatile("cp.async.commit_group;" ::: "memory")
#define CP_WAIT(N)   asm volatile("cp.async.wait_group %0;" :: "n"(N) : "memory")

__device__ __forceinline__ void ldmx4(uint32_t* r, uint32_t addr) {
    asm volatile("ldmatrix.sync.aligned.m8n8.x4.shared.b16 {%0,%1,%2,%3}, [%4];"
                 : "=r"(r[0]), "=r"(r[1]), "=r"(r[2]), "=r"(r[3]) : "r"(addr));
}
__device__ __forceinline__ void mma_bf16(float c[4], const uint32_t a[4],
                                         uint32_t b0, uint32_t b1) {
    asm volatile(
        "mma.sync.aligned.m16n8k16.row.col.f32.bf16.bf16.f32 "
        "{%0,%1,%2,%3}, {%4,%5,%6,%7}, {%8,%9}, {%0,%1,%2,%3};"
        : "+f"(c[0]), "+f"(c[1]), "+f"(c[2]), "+f"(c[3])
        : "r"(a[0]), "r"(a[1]), "r"(a[2]), "r"(a[3]), "r"(b0), "r"(b1));
}

// ---------------------------------------------------------------------------
// Kernel 1: fused prep.
//   blocks [0, 512):    per-node gather + tiny linear + tanh -> g_y (bf16)
//   blocks [512, 1536): Wf fp32 -> bf16 -> g_wf
// ---------------------------------------------------------------------------
#define R_PER_BLK  16
#define NODE_BLKS  (BATCH / R_PER_BLK)          // 512
#define CONV_BLKS  (ACTION * N_NODES / 1024)    // 1024

__global__ __launch_bounds__(256) void prep_kernel(
    const float* __restrict__ state, const float* __restrict__ W,
    const float* __restrict__ b,     const int*   __restrict__ idx,
    const float* __restrict__ Wf)
{
    if (blockIdx.x >= NODE_BLKS) {
        const int i = ((blockIdx.x - NODE_BLKS) * 256 + threadIdx.x) * 4;
        float4 v = *(const float4*)(Wf + i);
        __nv_bfloat162* p = (__nv_bfloat162*)(g_wf + i);
        p[0] = __floats2bfloat162_rn(v.x, v.y);
        p[1] = __floats2bfloat162_rn(v.z, v.w);
        return;
    }
    __shared__ float s[R_PER_BLK * STATE_DIM];
    const int t = threadIdx.x, row0 = blockIdx.x * R_PER_BLK;
    const float* sp = state + (long)row0 * STATE_DIM;
    for (int i = t; i < R_PER_BLK * STATE_DIM; i += 256) s[i] = sp[i];

    float w[ENTRIES]; int ix[ENTRIES];
#pragma unroll
    for (int e = 0; e < ENTRIES; e++) { w[e] = W[t*ENTRIES+e]; ix[e] = idx[t*ENTRIES+e]; }
    const float bb = b[t];
    __syncthreads();
#pragma unroll 4
    for (int r = 0; r < R_PER_BLK; r++) {
        const float* sr = s + r * STATE_DIM;
        float acc = bb;
#pragma unroll
        for (int e = 0; e < ENTRIES; e++) acc = fmaf(sr[ix[e]], w[e], acc);
        g_y[(long)(row0 + r) * N_NODES + t] = __float2bfloat16(tanhf(acc));
    }
}

// ---------------------------------------------------------------------------
// Kernel 2: out = 500*sigmoid(y @ Wf^T), bf16 mma.sync.m16n8k16.
// CTA tile 128x128, 128 threads (4 warps, 2x2), warp tile 64x64.
// 2 CTAs/SM (independent barrier domains hide sync/wait latency).
// BK=64, 2-stage cp.async pipeline + register double-buffered fragments
// (prefetch kc+1's ldmatrix during kc's 32 HMMAs).
// Smem rows padded to 144 B: conflict-free ldmatrix phases.
// ---------------------------------------------------------------------------
#define BK      64
#define ROWB    144                    // 72 bf16 per row
#define TILE_A  (128 * ROWB)           // 18432 B
#define STAGE_B (2 * TILE_A)           // A + B = 36864 B
#define SMEM_SZ (2 * STAGE_B)          // 73728 B

__global__ __launch_bounds__(128, 2) void gemm_sig_kernel(float* __restrict__ out)
{
    extern __shared__ char smem[];
    const uint32_t sb = smem_u32(smem);
    const int tid    = threadIdx.x;
    const int lane   = tid & 31;
    const int wid    = tid >> 5;
    const int warp_m = wid >> 1;       // 0..1
    const int warp_n = wid & 1;        // 0..1
    const int n0 = blockIdx.x * 128;
    const int m0 = blockIdx.y * 128;

    const __nv_bfloat16* gA = g_y  + (size_t)m0 * N_NODES;
    const __nv_bfloat16* gB = g_wf + (size_t)n0 * N_NODES;

    float acc[4][8][4] = {};

    uint32_t a_base[4];
#pragma unroll
    for (int mt = 0; mt < 4; mt++)
        a_base[mt] = sb + (warp_m * 64 + mt * 16 + (lane & 15)) * ROWB + (lane >> 4) * 16;
    uint32_t b_base[4];
#pragma unroll
    for (int p = 0; p < 4; p++)
        b_base[p] = sb + TILE_A
                  + (warp_n * 64 + p * 16 + ((lane >> 4) & 1) * 8 + (lane & 7)) * ROWB
                  + ((lane >> 3) & 1) * 16;

    // ---- prologue: stage 0 (1024 chunks per operand, 128 threads, 8 iters)
#pragma unroll
    for (int i = 0; i < 8; i++) {
        const int e = tid + i * 128, r = e >> 3, c = e & 7;
        const uint32_t so = r * ROWB + c * 16;
        CP_ASYNC16(sb + so,          (const void*)(gA + (size_t)r * N_NODES + c * 8));
        CP_ASYNC16(sb + TILE_A + so, (const void*)(gB + (size_t)r * N_NODES + c * 8));
    }
    CP_COMMIT();

    int buf = 0;
#pragma unroll
    for (int it = 0; it < 4; it++) {
        if (it < 3) {
            const int k0 = (it + 1) * BK;
            const uint32_t dst = sb + (buf ^ 1) * STAGE_B;
#pragma unroll
            for (int i = 0; i < 8; i++) {
                const int e = tid + i * 128, r = e >> 3, c = e & 7;
                const uint32_t so = r * ROWB + c * 16;
                CP_ASYNC16(dst + so,          (const void*)(gA + (size_t)r * N_NODES + k0 + c * 8));
                CP_ASYNC16(dst + TILE_A + so, (const void*)(gB + (size_t)r * N_NODES + k0 + c * 8));
            }
            CP_COMMIT();
            CP_WAIT(1);
        } else {
            CP_WAIT(0);
        }
        __syncthreads();

        const uint32_t soff = buf * STAGE_B;

        // fragment double buffer over kc
        uint32_t a[2][4][4], bp[2][4][4];
#pragma unroll
        for (int mt = 0; mt < 4; mt++) ldmx4(a[0][mt],  a_base[mt] + soff);
#pragma unroll
        for (int p = 0; p < 4; p++)    ldmx4(bp[0][p],  b_base[p]  + soff);

#pragma unroll
        for (int kc = 0; kc < 4; kc++) {
            const int cur = kc & 1, nxt = cur ^ 1;
            if (kc < 3) {
#pragma unroll
                for (int mt = 0; mt < 4; mt++) ldmx4(a[nxt][mt], a_base[mt] + soff + (kc + 1) * 32);
#pragma unroll
                for (int p = 0; p < 4; p++)    ldmx4(bp[nxt][p], b_base[p]  + soff + (kc + 1) * 32);
            }
#pragma unroll
            for (int mt = 0; mt < 4; mt++)
#pragma unroll
                for (int nt = 0; nt < 8; nt++)
                    mma_bf16(acc[mt][nt], a[cur][mt],
                             bp[cur][nt >> 1][(nt & 1) * 2], bp[cur][nt >> 1][(nt & 1) * 2 + 1]);
        }
        buf ^= 1;
        if (it < 3) __syncthreads();
    }

    // Epilogue: 500*sigmoid via MUFU rcp.
    const int frow = lane >> 2, fcol = lane & 3;
#pragma unroll
    for (int mt = 0; mt < 4; mt++) {
        const int m = m0 + warp_m * 64 + mt * 16 + frow;
#pragma unroll
        for (int nt = 0; nt < 8; nt++) {
            const int n = n0 + warp_n * 64 + nt * 8 + 2 * fcol;
            float2 o0, o1;
            o0.x = __fdividef(500.0f, 1.0f + __expf(-acc[mt][nt][0]));
            o0.y = __fdividef(500.0f, 1.0f + __expf(-acc[mt][nt][1]));
            o1.x = __fdividef(500.0f, 1.0f + __expf(-acc[mt][nt][2]));
            o1.y = __fdividef(500.0f, 1.0f + __expf(-acc[mt][nt][3]));
            *(float2*)&out[(size_t)m * ACTION + n]       = o0;
            *(float2*)&out[(size_t)(m + 8) * ACTION + n] = o1;
        }
    }
}

// ---------------------------------------------------------------------------
extern "C" void kernel_launch(void* const* d_in, const int* in_sizes, int n_in,
                              void* d_out, int out_size)
{
    const float* state = (const float*)d_in[0];
    const float* W     = (const float*)d_in[1];
    const float* b     = (const float*)d_in[2];
    const float* Wf    = (const float*)d_in[3];
    const int*   idx   = (const int*)  d_in[4];
    float*       out   = (float*)d_out;

    cudaFuncSetAttribute(gemm_sig_kernel,
                         cudaFuncAttributeMaxDynamicSharedMemorySize, SMEM_SZ);

    prep_kernel<<<NODE_BLKS + CONV_BLKS, 256>>>(state, W, b, idx, Wf);

    dim3 grid(ACTION / 128, BATCH / 128);
    gemm_sig_kernel<<<grid, 128, SMEM_SZ>>>(out);
}